// round 15
// baseline (speedup 1.0000x reference)
#include <cuda_runtime.h>
#include <math.h>

#define N_POSES    64
#define MAX_ATOMS  16384
#define POSE_SHIFT 14
#define NPAR       2048
#define EPS 1e-12f

#define THREADS 128
#define B_BOND  256
#define B_ANGLE 704
#define B_TOR   1408
#define B_TOTAL (B_BOND + B_ANGLE + B_TOR)   // 2368 = 16 * 148

// 16B-aligned coordinate scratch: one float4 per atom (w unused).
__device__ float4 g_coords4[N_POSES * MAX_ATOMS];

// Per-atom transpose: coalesced loads (12B lane stride) and stores (16B lane stride).
__global__ __launch_bounds__(256)
void transpose_kernel(const float* __restrict__ coords, float* __restrict__ out) {
    int i = blockIdx.x * blockDim.x + threadIdx.x;
    if (i < N_POSES * MAX_ATOMS) {
        const float* p = coords + 3 * i;
        float4 v = make_float4(__ldg(p), __ldg(p + 1), __ldg(p + 2), 0.0f);
        __stcg(&g_coords4[i], v);          // straight to L2 (gathers read from L2)
    }
    if (blockIdx.x == 0 && threadIdx.x < N_POSES) out[threadIdx.x] = 0.0f;
}

// L1-bypass gather: no reuse in L1 (16.8MB working set), serve from L2.
__device__ __forceinline__ float4 load_c4(int idx) {
    return __ldcg(&g_coords4[idx]);
}

__global__ __launch_bounds__(THREADS, 16)
void cartbonded_kernel(const float* __restrict__ gp,
                       const float* __restrict__ bond_x0,
                       const float* __restrict__ angle_x0,
                       const float* __restrict__ tor_x0,
                       const int*   __restrict__ bond_atoms,   // (NB,2)
                       const int*   __restrict__ bond_pidx,
                       const int*   __restrict__ angle_atoms,  // (NA,3)
                       const int*   __restrict__ angle_pidx,
                       const int*   __restrict__ tor_atoms,    // (NT,4)
                       const int*   __restrict__ tor_pidx,
                       int nb, int na, int nt,
                       float* __restrict__ out) {
    __shared__ float acc[2][N_POSES];     // parity-split accumulator
    __shared__ float sK[NPAR];            // 8 KB param table on the LDS path
    const int t = threadIdx.x;
    if (t < 2 * N_POSES) acc[t >> 6][t & 63] = 0.0f;
    {
        const float4* g4 = (const float4*)gp;
        float4* s4 = (float4*)sK;
        #pragma unroll
        for (int k = t; k < NPAR / 4; k += THREADS) s4[k] = __ldg(g4 + k);
    }
    __syncthreads();

    const int b = blockIdx.x;
    const int par = t & 1;                // lane parity -> accumulator copy

    if (b < B_BOND) {
        // ---------------- bonds ----------------
        const int stride = B_BOND * THREADS;
        for (int i = b * THREADS + t; i < nb; i += stride) {
            int2 a = __ldcs((const int2*)bond_atoms + i);
            float4 p0 = load_c4(a.x);
            float4 p1 = load_c4(a.y);
            float dx = p0.x - p1.x, dy = p0.y - p1.y, dz = p0.z - p1.z;
            float d = sqrtf(dx*dx + dy*dy + dz*dz + EPS);
            float diff = d - __ldcs(bond_x0 + i);
            float e = sK[__ldcs(bond_pidx + i)] * diff * diff;
            atomicAdd(&acc[par][a.x >> POSE_SHIFT], e);
        }
    } else if (b < B_BOND + B_ANGLE) {
        // ---------------- angles ----------------
        const int bb = b - B_BOND;
        const int stride = B_ANGLE * THREADS;
        for (int i = bb * THREADS + t; i < na; i += stride) {
            const int* ap = angle_atoms + 3 * i;
            int a0 = __ldcs(ap), a1 = __ldcs(ap + 1), a2 = __ldcs(ap + 2);
            float4 p0 = load_c4(a0);
            float4 p1 = load_c4(a1);
            float4 p2 = load_c4(a2);
            float ux = p0.x - p1.x, uy = p0.y - p1.y, uz = p0.z - p1.z;
            float vx = p2.x - p1.x, vy = p2.y - p1.y, vz = p2.z - p1.z;
            float cx = uy*vz - uz*vy;
            float cy = uz*vx - ux*vz;
            float cz = ux*vy - uy*vx;
            float snum = sqrtf(cx*cx + cy*cy + cz*cz + EPS);
            float dotuv = ux*vx + uy*vy + uz*vz;
            float theta = atan2f(snum, dotuv);
            float diff = theta - __ldcs(angle_x0 + i);
            float e = sK[__ldcs(angle_pidx + i)] * diff * diff;
            atomicAdd(&acc[par][a0 >> POSE_SHIFT], e);
        }
    } else {
        // ---------------- torsions ----------------
        const int bb = b - (B_BOND + B_ANGLE);
        const int stride = B_TOR * THREADS;
        for (int i = bb * THREADS + t; i < nt; i += stride) {
            int4 a = __ldcs((const int4*)tor_atoms + i);
            float4 p0 = load_c4(a.x);
            float4 p1 = load_c4(a.y);
            float4 p2 = load_c4(a.z);
            float4 p3 = load_c4(a.w);
            float b1x = p1.x - p0.x, b1y = p1.y - p0.y, b1z = p1.z - p0.z;
            float b2x = p2.x - p1.x, b2y = p2.y - p1.y, b2z = p2.z - p1.z;
            float b3x = p3.x - p2.x, b3y = p3.y - p2.y, b3z = p3.z - p2.z;
            // n1 = b1 x b2
            float n1x = b1y*b2z - b1z*b2y;
            float n1y = b1z*b2x - b1x*b2z;
            float n1z = b1x*b2y - b1y*b2x;
            // n2 = b2 x b3
            float n2x = b2y*b3z - b2z*b3y;
            float n2y = b2z*b3x - b2x*b3z;
            float n2z = b2x*b3y - b2y*b3x;
            float inv = rsqrtf(b2x*b2x + b2y*b2y + b2z*b2z + EPS);
            float bnx = b2x * inv, bny = b2y * inv, bnz = b2z * inv;
            // m1 = n1 x b2n
            float m1x = n1y*bnz - n1z*bny;
            float m1y = n1z*bnx - n1x*bnz;
            float m1z = n1x*bny - n1y*bnx;
            float sy = m1x*n2x + m1y*n2y + m1z*n2z;
            float sx = n1x*n2x + n1y*n2y + n1z*n2z;
            // cos(3*phi - x0) via triple-angle identities (no atan2/cos)
            float rh = rsqrtf(sx*sx + sy*sy + 1e-30f);
            float c = sx * rh, s = sy * rh;
            float cos3 = c * (4.0f*c*c - 3.0f);
            float sin3 = s * (3.0f - 4.0f*s*s);
            float cx0, sx0;
            __sincosf(__ldcs(tor_x0 + i), &sx0, &cx0);
            float e = sK[__ldcs(tor_pidx + i)] * (1.0f + cos3 * cx0 + sin3 * sx0);
            atomicAdd(&acc[par][a.x >> POSE_SHIFT], e);
        }
    }

    __syncthreads();
    if (t < N_POSES) atomicAdd(out + t, acc[0][t] + acc[1][t]);
}

extern "C" void kernel_launch(void* const* d_in, const int* in_sizes, int n_in,
                              void* d_out, int out_size) {
    const float* coords     = (const float*)d_in[0];
    const float* gp         = (const float*)d_in[1];
    const float* bond_x0    = (const float*)d_in[2];
    const float* angle_x0   = (const float*)d_in[3];
    const float* tor_x0     = (const float*)d_in[4];
    const int*   bond_atoms = (const int*)  d_in[5];
    const int*   bond_pidx  = (const int*)  d_in[6];
    const int*   angle_atoms= (const int*)  d_in[7];
    const int*   angle_pidx = (const int*)  d_in[8];
    const int*   tor_atoms  = (const int*)  d_in[9];
    const int*   tor_pidx   = (const int*)  d_in[10];

    const int nb = in_sizes[2];
    const int na = in_sizes[3];
    const int nt = in_sizes[4];

    float* out = (float*)d_out;

    const int natoms = N_POSES * MAX_ATOMS;
    transpose_kernel<<<(natoms + 255) / 256, 256>>>(coords, out);
    cartbonded_kernel<<<B_TOTAL, THREADS>>>(gp,
                                            bond_x0, angle_x0, tor_x0,
                                            bond_atoms, bond_pidx,
                                            angle_atoms, angle_pidx,
                                            tor_atoms, tor_pidx,
                                            nb, na, nt, out);
}

// round 17
// speedup vs baseline: 1.0195x; 1.0195x over previous
#include <cuda_runtime.h>
#include <math.h>

#define N_POSES    64
#define MAX_ATOMS  16384
#define POSE_SHIFT 14
#define NPAR       2048
#define NSPLIT     4
#define EPS 1e-12f

#define THREADS 256
#define B_BOND  128
#define B_ANGLE 352
#define B_TOR   704
#define B_TOTAL (B_BOND + B_ANGLE + B_TOR)   // 1184 = 8 * 148

// 16B-aligned coordinate scratch: one float4 per atom (w unused).
__device__ float4 g_coords4[N_POSES * MAX_ATOMS];

// Per-atom transpose: coalesced loads (12B lane stride) and stores (16B lane stride).
__global__ __launch_bounds__(256)
void transpose_kernel(const float* __restrict__ coords, float* __restrict__ out) {
    int i = blockIdx.x * blockDim.x + threadIdx.x;
    if (i < N_POSES * MAX_ATOMS) {
        const float* p = coords + 3 * i;
        float4 v = make_float4(__ldg(p), __ldg(p + 1), __ldg(p + 2), 0.0f);
        __stcg(&g_coords4[i], v);          // straight to L2 (gathers read from L2)
    }
    if (blockIdx.x == 0 && threadIdx.x < N_POSES) out[threadIdx.x] = 0.0f;
}

// L1-bypass gather: no reuse in L1 (16.8MB working set), serve from L2.
__device__ __forceinline__ float4 load_c4(int idx) {
    return __ldcg(&g_coords4[idx]);
}

__global__ __launch_bounds__(THREADS, 8)
void cartbonded_kernel(const float* __restrict__ gp,
                       const float* __restrict__ bond_x0,
                       const float* __restrict__ angle_x0,
                       const float* __restrict__ tor_x0,
                       const int*   __restrict__ bond_atoms,   // (NB,2)
                       const int*   __restrict__ bond_pidx,
                       const int*   __restrict__ angle_atoms,  // (NA,3)
                       const int*   __restrict__ angle_pidx,
                       const int*   __restrict__ tor_atoms,    // (NT,4)
                       const int*   __restrict__ tor_pidx,
                       int nb, int na, int nt,
                       float* __restrict__ out) {
    __shared__ float acc[NSPLIT][N_POSES];   // 4-way split accumulator (1 KB)
    __shared__ float sK[NPAR];               // 8 KB param table on the LDS path
    const int t = threadIdx.x;
    acc[t >> 6][t & 63] = 0.0f;              // 4*64 = 256 = THREADS
    {
        const float4* g4 = (const float4*)gp;
        float4* s4 = (float4*)sK;
        #pragma unroll
        for (int k = t; k < NPAR / 4; k += THREADS) s4[k] = __ldg(g4 + k);
    }
    __syncthreads();

    const int b = blockIdx.x;
    const int par = t & (NSPLIT - 1);        // lane low bits -> accumulator copy

    if (b < B_BOND) {
        // ---------------- bonds ----------------
        const int stride = B_BOND * THREADS;
        for (int i = b * THREADS + t; i < nb; i += stride) {
            int2 a = __ldcs((const int2*)bond_atoms + i);
            float4 p0 = load_c4(a.x);
            float4 p1 = load_c4(a.y);
            float dx = p0.x - p1.x, dy = p0.y - p1.y, dz = p0.z - p1.z;
            float d = sqrtf(dx*dx + dy*dy + dz*dz + EPS);
            float diff = d - __ldcs(bond_x0 + i);
            float e = sK[__ldcs(bond_pidx + i)] * diff * diff;
            atomicAdd(&acc[par][a.x >> POSE_SHIFT], e);
        }
    } else if (b < B_BOND + B_ANGLE) {
        // ---------------- angles ----------------
        const int bb = b - B_BOND;
        const int stride = B_ANGLE * THREADS;
        for (int i = bb * THREADS + t; i < na; i += stride) {
            const int* ap = angle_atoms + 3 * i;
            int a0 = __ldcs(ap), a1 = __ldcs(ap + 1), a2 = __ldcs(ap + 2);
            float4 p0 = load_c4(a0);
            float4 p1 = load_c4(a1);
            float4 p2 = load_c4(a2);
            float ux = p0.x - p1.x, uy = p0.y - p1.y, uz = p0.z - p1.z;
            float vx = p2.x - p1.x, vy = p2.y - p1.y, vz = p2.z - p1.z;
            float cx = uy*vz - uz*vy;
            float cy = uz*vx - ux*vz;
            float cz = ux*vy - uy*vx;
            float snum = sqrtf(cx*cx + cy*cy + cz*cz + EPS);
            float dotuv = ux*vx + uy*vy + uz*vz;
            float theta = atan2f(snum, dotuv);
            float diff = theta - __ldcs(angle_x0 + i);
            float e = sK[__ldcs(angle_pidx + i)] * diff * diff;
            atomicAdd(&acc[par][a0 >> POSE_SHIFT], e);
        }
    } else {
        // ---------------- torsions ----------------
        const int bb = b - (B_BOND + B_ANGLE);
        const int stride = B_TOR * THREADS;
        for (int i = bb * THREADS + t; i < nt; i += stride) {
            int4 a = __ldcs((const int4*)tor_atoms + i);
            float4 p0 = load_c4(a.x);
            float4 p1 = load_c4(a.y);
            float4 p2 = load_c4(a.z);
            float4 p3 = load_c4(a.w);
            float b1x = p1.x - p0.x, b1y = p1.y - p0.y, b1z = p1.z - p0.z;
            float b2x = p2.x - p1.x, b2y = p2.y - p1.y, b2z = p2.z - p1.z;
            float b3x = p3.x - p2.x, b3y = p3.y - p2.y, b3z = p3.z - p2.z;
            // n1 = b1 x b2
            float n1x = b1y*b2z - b1z*b2y;
            float n1y = b1z*b2x - b1x*b2z;
            float n1z = b1x*b2y - b1y*b2x;
            // n2 = b2 x b3
            float n2x = b2y*b3z - b2z*b3y;
            float n2y = b2z*b3x - b2x*b3z;
            float n2z = b2x*b3y - b2y*b3x;
            float inv = rsqrtf(b2x*b2x + b2y*b2y + b2z*b2z + EPS);
            float bnx = b2x * inv, bny = b2y * inv, bnz = b2z * inv;
            // m1 = n1 x b2n
            float m1x = n1y*bnz - n1z*bny;
            float m1y = n1z*bnx - n1x*bnz;
            float m1z = n1x*bny - n1y*bnx;
            float sy = m1x*n2x + m1y*n2y + m1z*n2z;
            float sx = n1x*n2x + n1y*n2y + n1z*n2z;
            // cos(3*phi - x0) via triple-angle identities (no atan2/cos)
            float rh = rsqrtf(sx*sx + sy*sy + 1e-30f);
            float c = sx * rh, s = sy * rh;
            float cos3 = c * (4.0f*c*c - 3.0f);
            float sin3 = s * (3.0f - 4.0f*s*s);
            float cx0, sx0;
            __sincosf(__ldcs(tor_x0 + i), &sx0, &cx0);
            float e = sK[__ldcs(tor_pidx + i)] * (1.0f + cos3 * cx0 + sin3 * sx0);
            atomicAdd(&acc[par][a.x >> POSE_SHIFT], e);
        }
    }

    __syncthreads();
    if (t < N_POSES)
        atomicAdd(out + t, (acc[0][t] + acc[1][t]) + (acc[2][t] + acc[3][t]));
}

extern "C" void kernel_launch(void* const* d_in, const int* in_sizes, int n_in,
                              void* d_out, int out_size) {
    const float* coords     = (const float*)d_in[0];
    const float* gp         = (const float*)d_in[1];
    const float* bond_x0    = (const float*)d_in[2];
    const float* angle_x0   = (const float*)d_in[3];
    const float* tor_x0     = (const float*)d_in[4];
    const int*   bond_atoms = (const int*)  d_in[5];
    const int*   bond_pidx  = (const int*)  d_in[6];
    const int*   angle_atoms= (const int*)  d_in[7];
    const int*   angle_pidx = (const int*)  d_in[8];
    const int*   tor_atoms  = (const int*)  d_in[9];
    const int*   tor_pidx   = (const int*)  d_in[10];

    const int nb = in_sizes[2];
    const int na = in_sizes[3];
    const int nt = in_sizes[4];

    float* out = (float*)d_out;

    const int natoms = N_POSES * MAX_ATOMS;
    transpose_kernel<<<(natoms + 255) / 256, 256>>>(coords, out);
    cartbonded_kernel<<<B_TOTAL, THREADS>>>(gp,
                                            bond_x0, angle_x0, tor_x0,
                                            bond_atoms, bond_pidx,
                                            angle_atoms, angle_pidx,
                                            tor_atoms, tor_pidx,
                                            nb, na, nt, out);
}